// round 6
// baseline (speedup 1.0000x reference)
#include <cuda_runtime.h>
#include <cuda_fp16.h>

#define N_NODES 50000
#define N_EDGES 800000
#define HID 128
#define N_GRAPHS 64
#define CAP 64          // padded CSR bucket capacity (P(deg>=64) ~ 1e-18)

// ---------------- scratch (static device globals; no allocation) ----------
__device__ float  g_bufA[N_NODES * HID];   // aggregated h1 (fp32)
__device__ float  g_bufB[N_NODES * HID];   // h2 (fp32)
__device__ __half g_h1[N_NODES * HID];     // h1 (fp16) - gathered by aggh
__device__ int    g_cur[N_NODES];          // in-degree (atomic bump)
__device__ int    g_csr[N_NODES * CAP];    // padded buckets of source ids
__device__ int2   g_csrw[N_NODES * CAP];   // packed (src, dinv[src])
__device__ float  g_dinv[N_NODES];
__device__ float  g_pool[N_GRAPHS * HID];
__device__ int    g_gcnt[N_GRAPHS];
__device__ int    g_is64;

// ---------------- helpers ---------------------------------------------------
__device__ __forceinline__ int ld_idx(const void* p, long long i, int is64) {
    if (is64) return (int)((const long long*)p)[i];
    return ((const int*)p)[i];
}

__device__ __forceinline__ void fma2(unsigned long long& d,
                                     unsigned long long a,
                                     unsigned long long b) {
    asm("fma.rn.f32x2 %0, %1, %2, %3;" : "=l"(d) : "l"(a), "l"(b), "l"(d));
}
__device__ __forceinline__ unsigned long long pack2(float x, float y) {
    unsigned long long r;
    asm("mov.b64 %0, {%1, %2};" : "=l"(r) : "f"(x), "f"(y));
    return r;
}
__device__ __forceinline__ void unpack2(unsigned long long v, float& x, float& y) {
    asm("mov.b64 {%0, %1}, %2;" : "=f"(x), "=f"(y) : "l"(v));
}

// convert uint2 (4 halves) -> 4 floats
__device__ __forceinline__ float4 h4_to_f4(uint2 v) {
    float2 a = __half22float2(*(const __half2*)&v.x);
    float2 b = __half22float2(*(const __half2*)&v.y);
    return make_float4(a.x, a.y, b.x, b.y);
}

// local int64/int32 detection from the first 64 index values (deterministic)
__device__ __forceinline__ int detect64(const void* ei, int tid, int* s_flag) {
    if (tid == 0) *s_flag = 1;
    __syncthreads();
    if (tid < 64) {
        long long v = ((const long long*)ei)[tid];
        if (v < 0 || v >= N_NODES) *s_flag = 0;
    }
    __syncthreads();
    return *s_flag;
}

// ---------------- kernels ---------------------------------------------------
__global__ void k_init() {
    int i = blockIdx.x * blockDim.x + threadIdx.x;
    if (i < N_NODES) g_cur[i] = 0;
    if (i < N_GRAPHS * HID) g_pool[i] = 0.f;
    if (i < N_GRAPHS) g_gcnt[i] = 0;
}

// single-pass padded-bucket CSR build
__global__ void k_build(const void* ei) {
    __shared__ int s_is64;
    int tid = threadIdx.x;
    int is64 = detect64(ei, tid, &s_is64);
    int e = blockIdx.x * blockDim.x + tid;
    if (e < N_EDGES) {
        int s = ld_idx(ei, e, is64);
        int d = ld_idx(ei, (long long)N_EDGES + e, is64);
        int slot = atomicAdd(&g_cur[d], 1);
        if (slot < CAP) g_csr[d * CAP + slot] = s;
    }
    if (blockIdx.x == 0 && tid == 0) g_is64 = is64;
}

__global__ void k_dinv() {
    int i = blockIdx.x * blockDim.x + threadIdx.x;
    if (i < N_NODES) g_dinv[i] = rsqrtf((float)(g_cur[i] + 1));  // +1 self-loop
}

// pack (src, dinv[src]) per edge slot — removes dependent dinv gathers later
__global__ void k_pack() {
    int i = (blockIdx.x * blockDim.x + threadIdx.x) >> 5;
    if (i >= N_NODES) return;
    int lane = threadIdx.x & 31;
    int deg = min(g_cur[i], CAP);
    int base = i * CAP;
    for (int e = lane; e < deg; e += 32) {
        int s = g_csr[base + e];
        g_csrw[base + e] = make_int2(s, __float_as_int(g_dinv[s]));
    }
}

// Fused layer 1: aggregate raw x (16-wide) + h1 = relu(xa@W1 + b1), fp16 out.
// One warp per node. 256 threads/block, W1 staged in smem.
__global__ void __launch_bounds__(256) k_l1(const float* __restrict__ x,
                                            const float* __restrict__ W1,
                                            const float* __restrict__ b1) {
    __shared__ float W1s[16 * 128];
    int tid = threadIdx.x;
    {   // stage W1 (2048 floats = 512 float4)
        float4* d4 = (float4*)W1s;
        const float4* s4 = (const float4*)W1;
        d4[tid] = s4[tid];
        d4[tid + 256] = s4[tid + 256];
    }
    __syncthreads();

    int i = (blockIdx.x * blockDim.x + tid) >> 5;
    int lane = tid & 31;
    if (i >= N_NODES) return;
    int half = lane >> 4;
    int col = lane & 15;
    float di = g_dinv[i];

    float acc = (half == 0) ? x[i * 16 + col] * di * di : 0.f;
    int base = i * CAP;
    int deg = min(g_cur[i], CAP);
    int e = 0;
    for (; e + 3 < deg; e += 4) {
        int2 p0 = g_csrw[base + e + half];
        int2 p1 = g_csrw[base + e + half + 2];
        float w0 = __int_as_float(p0.y) * di;
        float w1 = __int_as_float(p1.y) * di;
        acc += x[p0.x * 16 + col] * w0 + x[p1.x * 16 + col] * w1;
    }
    for (e += half; e < deg; e += 2) {
        int2 p = g_csrw[base + e];
        acc += x[p.x * 16 + col] * (__int_as_float(p.y) * di);
    }
    acc += __shfl_xor_sync(0xffffffffu, acc, 16);   // every lane: xa[lane&15]

    // h1 cols [4*lane, 4*lane+4): out = relu(sum_k xa[k] * W1[k][c] + b1[c])
    float4 o = make_float4(0.f, 0.f, 0.f, 0.f);
    const float4* W1s4 = (const float4*)W1s;
    #pragma unroll
    for (int k = 0; k < 16; k++) {
        float xk = __shfl_sync(0xffffffffu, acc, k);
        float4 w = W1s4[k * 32 + lane];
        o.x = fmaf(xk, w.x, o.x);
        o.y = fmaf(xk, w.y, o.y);
        o.z = fmaf(xk, w.z, o.z);
        o.w = fmaf(xk, w.w, o.w);
    }
    float4 bias = ((const float4*)b1)[lane];
    o.x = fmaxf(o.x + bias.x, 0.f);
    o.y = fmaxf(o.y + bias.y, 0.f);
    o.z = fmaxf(o.z + bias.z, 0.f);
    o.w = fmaxf(o.w + bias.w, 0.f);
    __half2 lo = __floats2half2_rn(o.x, o.y);
    __half2 hi = __floats2half2_rn(o.z, o.w);
    uint2 pk;
    pk.x = *(const unsigned int*)&lo;
    pk.y = *(const unsigned int*)&hi;
    ((uint2*)g_h1)[i * 32 + lane] = pk;
}

// Aggregate h1 (fp16, 128-wide): bufA_i = sum w_s*h1[s] + dinv_i^2*h1[i]
__global__ void k_aggh() {
    int i = (blockIdx.x * blockDim.x + threadIdx.x) >> 5;
    if (i >= N_NODES) return;
    int lane = threadIdx.x & 31;
    float di = g_dinv[i];
    const uint2* __restrict__ h = (const uint2*)g_h1;

    float4 v = h4_to_f4(h[i * 32 + lane]);
    float self = di * di;
    float4 acc = make_float4(v.x * self, v.y * self, v.z * self, v.w * self);

    int base = i * CAP;
    int deg = min(g_cur[i], CAP);
    int e = 0;
    for (; e + 2 <= deg; e += 2) {
        int2 p0 = g_csrw[base + e];
        int2 p1 = g_csrw[base + e + 1];
        float w0 = __int_as_float(p0.y) * di;
        float w1 = __int_as_float(p1.y) * di;
        float4 v0 = h4_to_f4(h[p0.x * 32 + lane]);
        float4 v1 = h4_to_f4(h[p1.x * 32 + lane]);
        acc.x += v0.x * w0 + v1.x * w1;
        acc.y += v0.y * w0 + v1.y * w1;
        acc.z += v0.z * w0 + v1.z * w1;
        acc.w += v0.w * w0 + v1.w * w1;
    }
    if (e < deg) {
        int2 p = g_csrw[base + e];
        float w = __int_as_float(p.y) * di;
        float4 v0 = h4_to_f4(h[p.x * 32 + lane]);
        acc.x += v0.x * w; acc.y += v0.y * w;
        acc.z += v0.z * w; acc.w += v0.w * w;
    }
    ((float4*)g_bufA)[i * 32 + lane] = acc;
}

// h2 = relu(bufA @ W2 + b2) -> bufB.  BM=64, BN=128, BK=16, 256 threads.
// Inner loop in packed fp32x2.
__global__ void k_gemm2(const float* __restrict__ W2, const float* __restrict__ b2) {
    __shared__ float As[16][64];
    __shared__ float Bs[16][128];
    int tid = threadIdx.x;
    int tx = tid & 31;
    int ty = tid >> 5;
    int row0 = blockIdx.x * 64;
    unsigned long long acc2[4][4];
    #pragma unroll
    for (int q = 0; q < 4; q++)
        #pragma unroll
        for (int c = 0; c < 4; c++) acc2[q][c] = 0ull;

    const float* A = g_bufA;
    for (int k0 = 0; k0 < 128; k0 += 16) {
        {
            int r = tid >> 2;
            int kq = (tid & 3) * 4;
            int row = row0 + r;
            float4 v = make_float4(0.f, 0.f, 0.f, 0.f);
            if (row < N_NODES)
                v = ((const float4*)A)[(row * 128 + k0 + kq) >> 2];
            As[kq + 0][r] = v.x;
            As[kq + 1][r] = v.y;
            As[kq + 2][r] = v.z;
            As[kq + 3][r] = v.w;
        }
        {
            const float4* W4 = (const float4*)(W2 + k0 * 128);
            float4* Bs4 = (float4*)&Bs[0][0];
            Bs4[tid] = W4[tid];
            Bs4[tid + 256] = W4[tid + 256];
        }
        __syncthreads();
        #pragma unroll
        for (int k = 0; k < 16; k++) {
            float4 b = *((float4*)&Bs[k][tx * 4]);
            unsigned long long bb[4];
            bb[0] = pack2(b.x, b.x);
            bb[1] = pack2(b.y, b.y);
            bb[2] = pack2(b.z, b.z);
            bb[3] = pack2(b.w, b.w);
            #pragma unroll
            for (int q = 0; q < 4; q++) {
                unsigned long long a2 =
                    *(const unsigned long long*)&As[k][ty * 8 + 2 * q];
                fma2(acc2[q][0], a2, bb[0]);
                fma2(acc2[q][1], a2, bb[1]);
                fma2(acc2[q][2], a2, bb[2]);
                fma2(acc2[q][3], a2, bb[3]);
            }
        }
        __syncthreads();
    }
    float4 bias = ((const float4*)b2)[tx];
    #pragma unroll
    for (int q = 0; q < 4; q++) {
        float lo[4], hi[4];
        #pragma unroll
        for (int c = 0; c < 4; c++) unpack2(acc2[q][c], lo[c], hi[c]);
        int r0 = row0 + ty * 8 + 2 * q;
        if (r0 < N_NODES) {
            float4 v = make_float4(fmaxf(lo[0] + bias.x, 0.f),
                                   fmaxf(lo[1] + bias.y, 0.f),
                                   fmaxf(lo[2] + bias.z, 0.f),
                                   fmaxf(lo[3] + bias.w, 0.f));
            ((float4*)g_bufB)[r0 * 32 + tx] = v;
        }
        if (r0 + 1 < N_NODES) {
            float4 v = make_float4(fmaxf(hi[0] + bias.x, 0.f),
                                   fmaxf(hi[1] + bias.y, 0.f),
                                   fmaxf(hi[2] + bias.z, 0.f),
                                   fmaxf(hi[3] + bias.w, 0.f));
            ((float4*)g_bufB)[(r0 + 1) * 32 + tx] = v;
        }
    }
}

// pool sums from bufB (batch sorted -> local accumulation); also graph counts.
__global__ void k_pool(const void* batch) {
    int tid = threadIdx.x;
    int start = blockIdx.x * 128;
    int end = min(start + 128, N_NODES);
    if (start >= N_NODES) return;
    int is64 = g_is64;
    int curg = ld_idx(batch, start, is64);
    float acc = 0.f;
    int runlen = 0;
    for (int n = start; n < end; n++) {
        int g = ld_idx(batch, n, is64);
        if (g != curg) {
            atomicAdd(&g_pool[curg * 128 + tid], acc);
            if (tid == 0) atomicAdd(&g_gcnt[curg], runlen);
            acc = 0.f; runlen = 0;
            curg = g;
        }
        acc += g_bufB[n * 128 + tid];
        runlen++;
    }
    atomicAdd(&g_pool[curg * 128 + tid], acc);
    if (tid == 0) atomicAdd(&g_gcnt[curg], runlen);
}

__global__ void k_final(const float* __restrict__ Wfc,
                        const float* __restrict__ bfc,
                        float* __restrict__ out) {
    int tid = threadIdx.x;   // 1024 = 64*16
    int g = tid >> 4;
    int o = tid & 15;
    float c = (float)max(g_gcnt[g], 1);
    float s = 0.f;
    #pragma unroll 8
    for (int k = 0; k < 128; k++)
        s = fmaf(g_pool[g * 128 + k], Wfc[k * 16 + o], s);
    out[tid] = s / c + bfc[o];
}

// ---------------- launch ----------------------------------------------------
extern "C" void kernel_launch(void* const* d_in, const int* in_sizes, int n_in,
                              void* d_out, int out_size) {
    const float* x   = (const float*)d_in[0];
    const void*  ei  = d_in[1];
    const void*  bat = d_in[2];
    const float* W1  = (const float*)d_in[3];
    const float* b1  = (const float*)d_in[4];
    const float* W2  = (const float*)d_in[5];
    const float* b2  = (const float*)d_in[6];
    const float* Wfc = (const float*)d_in[7];
    const float* bfc = (const float*)d_in[8];
    float* out = (float*)d_out;

    k_init<<<(N_NODES + 255) / 256, 256>>>();                 // 1
    k_build<<<(N_EDGES + 255) / 256, 256>>>(ei);              // 2
    k_dinv<<<(N_NODES + 255) / 256, 256>>>();                 // 3
    k_pack<<<(N_NODES * 32 + 255) / 256, 256>>>();            // 4
    k_l1<<<(N_NODES * 32 + 255) / 256, 256>>>(x, W1, b1);     // 5
    k_aggh<<<(N_NODES + 7) / 8, 256>>>();                     // 6
    k_gemm2<<<(N_NODES + 63) / 64, 256>>>(W2, b2);            // 7
    k_pool<<<(N_NODES + 127) / 128, 128>>>(bat);              // 8
    k_final<<<1, 1024>>>(Wfc, bfc, out);                      // 9
}

// round 7
// speedup vs baseline: 1.0740x; 1.0740x over previous
#include <cuda_runtime.h>
#include <cuda_fp16.h>

#define N_NODES 50000
#define N_EDGES 800000
#define HID 128
#define N_GRAPHS 64
#define CAP 64          // padded CSR bucket capacity (P(deg>=64) ~ 1e-18)

// ---------------- scratch (static device globals; no allocation) ----------
__device__ float  g_bufA[N_NODES * HID];   // aggregated h1 (fp32)
__device__ float  g_bufB[N_NODES * HID];   // h2 (fp32)
__device__ __half g_h1[N_NODES * HID];     // h1 (fp16) - gathered by aggh
__device__ int    g_cur[N_NODES];          // in-degree (atomic bump)
__device__ int    g_csr[N_NODES * CAP];    // padded buckets of source ids
__device__ float  g_dinv[N_NODES];
__device__ float  g_pool[N_GRAPHS * HID];
__device__ int    g_gcnt[N_GRAPHS];
__device__ int    g_is64;

// ---------------- helpers ---------------------------------------------------
__device__ __forceinline__ int ld_idx(const void* p, long long i, int is64) {
    if (is64) return (int)((const long long*)p)[i];
    return ((const int*)p)[i];
}

__device__ __forceinline__ void fma2(unsigned long long& d,
                                     unsigned long long a,
                                     unsigned long long b) {
    asm("fma.rn.f32x2 %0, %1, %2, %3;" : "=l"(d) : "l"(a), "l"(b), "l"(d));
}
__device__ __forceinline__ unsigned long long pack2(float x, float y) {
    unsigned long long r;
    asm("mov.b64 %0, {%1, %2};" : "=l"(r) : "f"(x), "f"(y));
    return r;
}
__device__ __forceinline__ void unpack2(unsigned long long v, float& x, float& y) {
    asm("mov.b64 {%0, %1}, %2;" : "=f"(x), "=f"(y) : "l"(v));
}

// convert uint2 (4 halves) -> 4 floats
__device__ __forceinline__ float4 h4_to_f4(uint2 v) {
    float2 a = __half22float2(*(const __half2*)&v.x);
    float2 b = __half22float2(*(const __half2*)&v.y);
    return make_float4(a.x, a.y, b.x, b.y);
}

// local int64/int32 detection from the first 64 index values (deterministic)
__device__ __forceinline__ int detect64(const void* ei, int tid, int* s_flag) {
    if (tid == 0) *s_flag = 1;
    __syncthreads();
    if (tid < 64) {
        long long v = ((const long long*)ei)[tid];
        if (v < 0 || v >= N_NODES) *s_flag = 0;
    }
    __syncthreads();
    return *s_flag;
}

// ---------------- kernels ---------------------------------------------------
__global__ void k_init() {
    int i = blockIdx.x * blockDim.x + threadIdx.x;
    if (i < N_NODES) g_cur[i] = 0;
    if (i < N_GRAPHS * HID) g_pool[i] = 0.f;
    if (i < N_GRAPHS) g_gcnt[i] = 0;
}

// single-pass padded-bucket CSR build
__global__ void k_build(const void* ei) {
    __shared__ int s_is64;
    int tid = threadIdx.x;
    int is64 = detect64(ei, tid, &s_is64);
    int e = blockIdx.x * blockDim.x + tid;
    if (e < N_EDGES) {
        int s = ld_idx(ei, e, is64);
        int d = ld_idx(ei, (long long)N_EDGES + e, is64);
        int slot = atomicAdd(&g_cur[d], 1);
        if (slot < CAP) g_csr[d * CAP + slot] = s;
    }
    if (blockIdx.x == 0 && tid == 0) g_is64 = is64;
}

__global__ void k_dinv() {
    int i = blockIdx.x * blockDim.x + threadIdx.x;
    if (i < N_NODES) g_dinv[i] = rsqrtf((float)(g_cur[i] + 1));  // +1 self-loop
}

// Fused layer 1: aggregate raw x (16-wide) + h1 = relu(xa@W1 + b1), fp16 out.
// One warp per node. 256 threads/block, W1 staged in smem.
__global__ void __launch_bounds__(256) k_l1(const float* __restrict__ x,
                                            const float* __restrict__ W1,
                                            const float* __restrict__ b1) {
    __shared__ float W1s[16 * 128];
    int tid = threadIdx.x;
    {   // stage W1 (2048 floats = 512 float4)
        float4* d4 = (float4*)W1s;
        const float4* s4 = (const float4*)W1;
        d4[tid] = s4[tid];
        d4[tid + 256] = s4[tid + 256];
    }
    __syncthreads();

    int i = (blockIdx.x * blockDim.x + tid) >> 5;
    int lane = tid & 31;
    if (i >= N_NODES) return;
    int half = lane >> 4;
    int col = lane & 15;
    float di = g_dinv[i];

    float acc = (half == 0) ? x[i * 16 + col] * di * di : 0.f;
    int base = i * CAP;
    int deg = min(g_cur[i], CAP);
    int e = 0;
    for (; e + 3 < deg; e += 4) {
        int s0 = g_csr[base + e + half];
        int s1 = g_csr[base + e + half + 2];
        float w0 = g_dinv[s0] * di;
        float w1 = g_dinv[s1] * di;
        acc += x[s0 * 16 + col] * w0 + x[s1 * 16 + col] * w1;
    }
    for (e += half; e < deg; e += 2) {
        int s = g_csr[base + e];
        acc += x[s * 16 + col] * (g_dinv[s] * di);
    }
    acc += __shfl_xor_sync(0xffffffffu, acc, 16);   // every lane: xa[lane&15]

    // h1 cols [4*lane, 4*lane+4): out = relu(sum_k xa[k] * W1[k][c] + b1[c])
    float4 o = make_float4(0.f, 0.f, 0.f, 0.f);
    const float4* W1s4 = (const float4*)W1s;
    #pragma unroll
    for (int k = 0; k < 16; k++) {
        float xk = __shfl_sync(0xffffffffu, acc, k);
        float4 w = W1s4[k * 32 + lane];
        o.x = fmaf(xk, w.x, o.x);
        o.y = fmaf(xk, w.y, o.y);
        o.z = fmaf(xk, w.z, o.z);
        o.w = fmaf(xk, w.w, o.w);
    }
    float4 bias = ((const float4*)b1)[lane];
    o.x = fmaxf(o.x + bias.x, 0.f);
    o.y = fmaxf(o.y + bias.y, 0.f);
    o.z = fmaxf(o.z + bias.z, 0.f);
    o.w = fmaxf(o.w + bias.w, 0.f);
    __half2 lo = __floats2half2_rn(o.x, o.y);
    __half2 hi = __floats2half2_rn(o.z, o.w);
    uint2 pk;
    pk.x = *(const unsigned int*)&lo;
    pk.y = *(const unsigned int*)&hi;
    ((uint2*)g_h1)[i * 32 + lane] = pk;
}

// Aggregate h1 (fp16, 128-wide): bufA_i = sum w_s*h1[s] + dinv_i^2*h1[i]
// 4 edges in flight per warp for MLP.
__global__ void k_aggh() {
    int i = (blockIdx.x * blockDim.x + threadIdx.x) >> 5;
    if (i >= N_NODES) return;
    int lane = threadIdx.x & 31;
    float di = g_dinv[i];
    const uint2* __restrict__ h = (const uint2*)g_h1;

    float4 v = h4_to_f4(h[i * 32 + lane]);
    float self = di * di;
    float4 acc = make_float4(v.x * self, v.y * self, v.z * self, v.w * self);

    int base = i * CAP;
    int deg = min(g_cur[i], CAP);
    int e = 0;
    for (; e + 4 <= deg; e += 4) {
        int s0 = g_csr[base + e + 0], s1 = g_csr[base + e + 1];
        int s2 = g_csr[base + e + 2], s3 = g_csr[base + e + 3];
        float w0 = g_dinv[s0] * di, w1 = g_dinv[s1] * di;
        float w2 = g_dinv[s2] * di, w3 = g_dinv[s3] * di;
        float4 v0 = h4_to_f4(h[s0 * 32 + lane]);
        float4 v1 = h4_to_f4(h[s1 * 32 + lane]);
        float4 v2 = h4_to_f4(h[s2 * 32 + lane]);
        float4 v3 = h4_to_f4(h[s3 * 32 + lane]);
        acc.x += v0.x * w0 + v1.x * w1 + v2.x * w2 + v3.x * w3;
        acc.y += v0.y * w0 + v1.y * w1 + v2.y * w2 + v3.y * w3;
        acc.z += v0.z * w0 + v1.z * w1 + v2.z * w2 + v3.z * w3;
        acc.w += v0.w * w0 + v1.w * w1 + v2.w * w2 + v3.w * w3;
    }
    for (; e < deg; e++) {
        int s = g_csr[base + e];
        float w = g_dinv[s] * di;
        float4 v0 = h4_to_f4(h[s * 32 + lane]);
        acc.x += v0.x * w; acc.y += v0.y * w;
        acc.z += v0.z * w; acc.w += v0.w * w;
    }
    ((float4*)g_bufA)[i * 32 + lane] = acc;
}

// h2 = relu(bufA @ W2 + b2) -> bufB.  BM=64, BN=128, BK=16, 256 threads.
// Inner loop in packed fp32x2.
__global__ void k_gemm2(const float* __restrict__ W2, const float* __restrict__ b2) {
    __shared__ float As[16][64];
    __shared__ float Bs[16][128];
    int tid = threadIdx.x;
    int tx = tid & 31;
    int ty = tid >> 5;
    int row0 = blockIdx.x * 64;
    unsigned long long acc2[4][4];
    #pragma unroll
    for (int q = 0; q < 4; q++)
        #pragma unroll
        for (int c = 0; c < 4; c++) acc2[q][c] = 0ull;

    const float* A = g_bufA;
    for (int k0 = 0; k0 < 128; k0 += 16) {
        {
            int r = tid >> 2;
            int kq = (tid & 3) * 4;
            int row = row0 + r;
            float4 v = make_float4(0.f, 0.f, 0.f, 0.f);
            if (row < N_NODES)
                v = ((const float4*)A)[(row * 128 + k0 + kq) >> 2];
            As[kq + 0][r] = v.x;
            As[kq + 1][r] = v.y;
            As[kq + 2][r] = v.z;
            As[kq + 3][r] = v.w;
        }
        {
            const float4* W4 = (const float4*)(W2 + k0 * 128);
            float4* Bs4 = (float4*)&Bs[0][0];
            Bs4[tid] = W4[tid];
            Bs4[tid + 256] = W4[tid + 256];
        }
        __syncthreads();
        #pragma unroll
        for (int k = 0; k < 16; k++) {
            float4 b = *((float4*)&Bs[k][tx * 4]);
            unsigned long long bb[4];
            bb[0] = pack2(b.x, b.x);
            bb[1] = pack2(b.y, b.y);
            bb[2] = pack2(b.z, b.z);
            bb[3] = pack2(b.w, b.w);
            #pragma unroll
            for (int q = 0; q < 4; q++) {
                unsigned long long a2 =
                    *(const unsigned long long*)&As[k][ty * 8 + 2 * q];
                fma2(acc2[q][0], a2, bb[0]);
                fma2(acc2[q][1], a2, bb[1]);
                fma2(acc2[q][2], a2, bb[2]);
                fma2(acc2[q][3], a2, bb[3]);
            }
        }
        __syncthreads();
    }
    float4 bias = ((const float4*)b2)[tx];
    #pragma unroll
    for (int q = 0; q < 4; q++) {
        float lo[4], hi[4];
        #pragma unroll
        for (int c = 0; c < 4; c++) unpack2(acc2[q][c], lo[c], hi[c]);
        int r0 = row0 + ty * 8 + 2 * q;
        if (r0 < N_NODES) {
            float4 v = make_float4(fmaxf(lo[0] + bias.x, 0.f),
                                   fmaxf(lo[1] + bias.y, 0.f),
                                   fmaxf(lo[2] + bias.z, 0.f),
                                   fmaxf(lo[3] + bias.w, 0.f));
            ((float4*)g_bufB)[r0 * 32 + tx] = v;
        }
        if (r0 + 1 < N_NODES) {
            float4 v = make_float4(fmaxf(hi[0] + bias.x, 0.f),
                                   fmaxf(hi[1] + bias.y, 0.f),
                                   fmaxf(hi[2] + bias.z, 0.f),
                                   fmaxf(hi[3] + bias.w, 0.f));
            ((float4*)g_bufB)[(r0 + 1) * 32 + tx] = v;
        }
    }
}

// pool sums from bufB (batch sorted -> local accumulation); also graph counts.
__global__ void k_pool(const void* batch) {
    int tid = threadIdx.x;
    int start = blockIdx.x * 128;
    int end = min(start + 128, N_NODES);
    if (start >= N_NODES) return;
    int is64 = g_is64;
    int curg = ld_idx(batch, start, is64);
    float acc = 0.f;
    int runlen = 0;
    for (int n = start; n < end; n++) {
        int g = ld_idx(batch, n, is64);
        if (g != curg) {
            atomicAdd(&g_pool[curg * 128 + tid], acc);
            if (tid == 0) atomicAdd(&g_gcnt[curg], runlen);
            acc = 0.f; runlen = 0;
            curg = g;
        }
        acc += g_bufB[n * 128 + tid];
        runlen++;
    }
    atomicAdd(&g_pool[curg * 128 + tid], acc);
    if (tid == 0) atomicAdd(&g_gcnt[curg], runlen);
}

__global__ void k_final(const float* __restrict__ Wfc,
                        const float* __restrict__ bfc,
                        float* __restrict__ out) {
    int tid = threadIdx.x;   // 1024 = 64*16
    int g = tid >> 4;
    int o = tid & 15;
    float c = (float)max(g_gcnt[g], 1);
    float s = 0.f;
    #pragma unroll 8
    for (int k = 0; k < 128; k++)
        s = fmaf(g_pool[g * 128 + k], Wfc[k * 16 + o], s);
    out[tid] = s / c + bfc[o];
}

// ---------------- launch ----------------------------------------------------
extern "C" void kernel_launch(void* const* d_in, const int* in_sizes, int n_in,
                              void* d_out, int out_size) {
    const float* x   = (const float*)d_in[0];
    const void*  ei  = d_in[1];
    const void*  bat = d_in[2];
    const float* W1  = (const float*)d_in[3];
    const float* b1  = (const float*)d_in[4];
    const float* W2  = (const float*)d_in[5];
    const float* b2  = (const float*)d_in[6];
    const float* Wfc = (const float*)d_in[7];
    const float* bfc = (const float*)d_in[8];
    float* out = (float*)d_out;

    k_init<<<(N_NODES + 255) / 256, 256>>>();                 // 1
    k_build<<<(N_EDGES + 255) / 256, 256>>>(ei);              // 2
    k_dinv<<<(N_NODES + 255) / 256, 256>>>();                 // 3
    k_l1<<<(N_NODES * 32 + 255) / 256, 256>>>(x, W1, b1);     // 4  <- ncu slot
    k_aggh<<<(N_NODES + 7) / 8, 256>>>();                     // 5
    k_gemm2<<<(N_NODES + 63) / 64, 256>>>(W2, b2);            // 6
    k_pool<<<(N_NODES + 127) / 128, 128>>>(bat);              // 7
    k_final<<<1, 1024>>>(Wfc, bfc, out);                      // 8
}

// round 8
// speedup vs baseline: 1.1155x; 1.0386x over previous
#include <cuda_runtime.h>
#include <cuda_fp16.h>

#define N_NODES 50000
#define N_EDGES 800000
#define HID 128
#define N_GRAPHS 64
#define CAP 64          // padded CSR bucket capacity (P(deg>=64) ~ 1e-18)

// ---------------- scratch (static device globals; no allocation) ----------
__device__ float  g_bufA[N_NODES * HID];   // aggregated h1 (fp32)
__device__ float  g_bufB[N_NODES * HID];   // h2 (fp32)
__device__ __half g_hs[N_NODES * HID];     // dinv_i * h1_i (fp16) - gathered by aggh
__device__ float  g_xs[N_NODES * 16];      // dinv_i * x_i
__device__ int    g_cur[N_NODES];          // in-degree (atomic bump)
__device__ int    g_csr[N_NODES * CAP];    // padded buckets of source ids
__device__ float  g_dinv[N_NODES];
__device__ float  g_pool[N_GRAPHS * HID];
__device__ int    g_gcnt[N_GRAPHS];
__device__ int    g_is64;

// ---------------- helpers ---------------------------------------------------
__device__ __forceinline__ int ld_idx(const void* p, long long i, int is64) {
    if (is64) return (int)((const long long*)p)[i];
    return ((const int*)p)[i];
}

__device__ __forceinline__ void fma2(unsigned long long& d,
                                     unsigned long long a,
                                     unsigned long long b) {
    asm("fma.rn.f32x2 %0, %1, %2, %3;" : "=l"(d) : "l"(a), "l"(b), "l"(d));
}
__device__ __forceinline__ unsigned long long pack2(float x, float y) {
    unsigned long long r;
    asm("mov.b64 %0, {%1, %2};" : "=l"(r) : "f"(x), "f"(y));
    return r;
}
__device__ __forceinline__ void unpack2(unsigned long long v, float& x, float& y) {
    asm("mov.b64 {%0, %1}, %2;" : "=f"(x), "=f"(y) : "l"(v));
}

// convert uint2 (4 halves) -> 4 floats
__device__ __forceinline__ float4 h4_to_f4(uint2 v) {
    float2 a = __half22float2(*(const __half2*)&v.x);
    float2 b = __half22float2(*(const __half2*)&v.y);
    return make_float4(a.x, a.y, b.x, b.y);
}

// local int64/int32 detection from the first 64 index values (deterministic)
__device__ __forceinline__ int detect64(const void* ei, int tid, int* s_flag) {
    if (tid == 0) *s_flag = 1;
    __syncthreads();
    if (tid < 64) {
        long long v = ((const long long*)ei)[tid];
        if (v < 0 || v >= N_NODES) *s_flag = 0;
    }
    __syncthreads();
    return *s_flag;
}

// ---------------- kernels ---------------------------------------------------
__global__ void k_init() {
    int i = blockIdx.x * blockDim.x + threadIdx.x;
    if (i < N_NODES) g_cur[i] = 0;
    if (i < N_GRAPHS * HID) g_pool[i] = 0.f;
    if (i < N_GRAPHS) g_gcnt[i] = 0;
}

// single-pass padded-bucket CSR build
__global__ void k_build(const void* ei) {
    __shared__ int s_is64;
    int tid = threadIdx.x;
    int is64 = detect64(ei, tid, &s_is64);
    int e = blockIdx.x * blockDim.x + tid;
    if (e < N_EDGES) {
        int s = ld_idx(ei, e, is64);
        int d = ld_idx(ei, (long long)N_EDGES + e, is64);
        int slot = atomicAdd(&g_cur[d], 1);
        if (slot < CAP) g_csr[d * CAP + slot] = s;
    }
    if (blockIdx.x == 0 && tid == 0) g_is64 = is64;
}

// dinv + pre-scaled features xs = dinv_i * x_i (one warp per 2 nodes: 16 cols each)
__global__ void k_dinvxs(const float* __restrict__ x) {
    int t = blockIdx.x * blockDim.x + threadIdx.x;
    int i = t >> 4;                 // node
    int col = t & 15;
    if (i >= N_NODES) return;
    float di = rsqrtf((float)(g_cur[i] + 1));   // +1 self-loop
    if (col == 0) g_dinv[i] = di;
    g_xs[i * 16 + col] = x[i * 16 + col] * di;
}

// Fused layer 1: xa_i = di*(xs[i] + sum_e xs[s]); h1 = relu(xa@W1 + b1);
// emit hs = di*h1 (fp16). One warp per node, W1 staged in smem.
// Per-edge loop body: csr load + xs gather + add (no dinv, no multiply).
__global__ void __launch_bounds__(256) k_l1(const float* __restrict__ W1,
                                            const float* __restrict__ b1) {
    __shared__ float W1s[16 * 128];
    int tid = threadIdx.x;
    {   // stage W1 (2048 floats = 512 float4)
        float4* d4 = (float4*)W1s;
        const float4* s4 = (const float4*)W1;
        d4[tid] = s4[tid];
        d4[tid + 256] = s4[tid + 256];
    }
    __syncthreads();

    int i = (blockIdx.x * blockDim.x + tid) >> 5;
    int lane = tid & 31;
    if (i >= N_NODES) return;
    int half = lane >> 4;
    int col = lane & 15;
    float di = g_dinv[i];

    float acc = (half == 0) ? g_xs[i * 16 + col] : 0.f;   // self term
    int base = i * CAP;
    int deg = min(g_cur[i], CAP);
    int e = 0;
    for (; e + 3 < deg; e += 4) {
        int s0 = g_csr[base + e + half];
        int s1 = g_csr[base + e + half + 2];
        acc += g_xs[s0 * 16 + col] + g_xs[s1 * 16 + col];
    }
    for (e += half; e < deg; e += 2) {
        int s = g_csr[base + e];
        acc += g_xs[s * 16 + col];
    }
    acc += __shfl_xor_sync(0xffffffffu, acc, 16);
    acc *= di;                                   // xa[col] on every lane pair

    // h1 cols [4*lane, 4*lane+4): out = relu(sum_k xa[k] * W1[k][c] + b1[c])
    float4 o = make_float4(0.f, 0.f, 0.f, 0.f);
    const float4* W1s4 = (const float4*)W1s;
    #pragma unroll
    for (int k = 0; k < 16; k++) {
        float xk = __shfl_sync(0xffffffffu, acc, k);
        float4 w = W1s4[k * 32 + lane];
        o.x = fmaf(xk, w.x, o.x);
        o.y = fmaf(xk, w.y, o.y);
        o.z = fmaf(xk, w.z, o.z);
        o.w = fmaf(xk, w.w, o.w);
    }
    float4 bias = ((const float4*)b1)[lane];
    o.x = fmaxf(o.x + bias.x, 0.f) * di;    // hs = dinv_i * relu(h1)
    o.y = fmaxf(o.y + bias.y, 0.f) * di;
    o.z = fmaxf(o.z + bias.z, 0.f) * di;
    o.w = fmaxf(o.w + bias.w, 0.f) * di;
    __half2 lo = __floats2half2_rn(o.x, o.y);
    __half2 hi = __floats2half2_rn(o.z, o.w);
    uint2 pk;
    pk.x = *(const unsigned int*)&lo;
    pk.y = *(const unsigned int*)&hi;
    ((uint2*)g_hs)[i * 32 + lane] = pk;
}

// Aggregate hs (fp16): bufA_i = di * (hs[i] + sum_e hs[s])
// Per-edge body: csr load + hs gather + add. 4 edges in flight.
__global__ void k_aggh() {
    int i = (blockIdx.x * blockDim.x + threadIdx.x) >> 5;
    if (i >= N_NODES) return;
    int lane = threadIdx.x & 31;
    float di = g_dinv[i];
    const uint2* __restrict__ h = (const uint2*)g_hs;

    float4 acc = h4_to_f4(h[i * 32 + lane]);    // self term

    int base = i * CAP;
    int deg = min(g_cur[i], CAP);
    int e = 0;
    for (; e + 4 <= deg; e += 4) {
        int s0 = g_csr[base + e + 0], s1 = g_csr[base + e + 1];
        int s2 = g_csr[base + e + 2], s3 = g_csr[base + e + 3];
        float4 v0 = h4_to_f4(h[s0 * 32 + lane]);
        float4 v1 = h4_to_f4(h[s1 * 32 + lane]);
        float4 v2 = h4_to_f4(h[s2 * 32 + lane]);
        float4 v3 = h4_to_f4(h[s3 * 32 + lane]);
        acc.x += (v0.x + v1.x) + (v2.x + v3.x);
        acc.y += (v0.y + v1.y) + (v2.y + v3.y);
        acc.z += (v0.z + v1.z) + (v2.z + v3.z);
        acc.w += (v0.w + v1.w) + (v2.w + v3.w);
    }
    for (; e < deg; e++) {
        int s = g_csr[base + e];
        float4 v0 = h4_to_f4(h[s * 32 + lane]);
        acc.x += v0.x; acc.y += v0.y; acc.z += v0.z; acc.w += v0.w;
    }
    acc.x *= di; acc.y *= di; acc.z *= di; acc.w *= di;
    ((float4*)g_bufA)[i * 32 + lane] = acc;
}

// h2 = relu(bufA @ W2 + b2) -> bufB.  BM=64, BN=128, BK=16, 256 threads.
// Inner loop in packed fp32x2.
__global__ void k_gemm2(const float* __restrict__ W2, const float* __restrict__ b2) {
    __shared__ float As[16][64];
    __shared__ float Bs[16][128];
    int tid = threadIdx.x;
    int tx = tid & 31;
    int ty = tid >> 5;
    int row0 = blockIdx.x * 64;
    unsigned long long acc2[4][4];
    #pragma unroll
    for (int q = 0; q < 4; q++)
        #pragma unroll
        for (int c = 0; c < 4; c++) acc2[q][c] = 0ull;

    const float* A = g_bufA;
    for (int k0 = 0; k0 < 128; k0 += 16) {
        {
            int r = tid >> 2;
            int kq = (tid & 3) * 4;
            int row = row0 + r;
            float4 v = make_float4(0.f, 0.f, 0.f, 0.f);
            if (row < N_NODES)
                v = ((const float4*)A)[(row * 128 + k0 + kq) >> 2];
            As[kq + 0][r] = v.x;
            As[kq + 1][r] = v.y;
            As[kq + 2][r] = v.z;
            As[kq + 3][r] = v.w;
        }
        {
            const float4* W4 = (const float4*)(W2 + k0 * 128);
            float4* Bs4 = (float4*)&Bs[0][0];
            Bs4[tid] = W4[tid];
            Bs4[tid + 256] = W4[tid + 256];
        }
        __syncthreads();
        #pragma unroll
        for (int k = 0; k < 16; k++) {
            float4 b = *((float4*)&Bs[k][tx * 4]);
            unsigned long long bb[4];
            bb[0] = pack2(b.x, b.x);
            bb[1] = pack2(b.y, b.y);
            bb[2] = pack2(b.z, b.z);
            bb[3] = pack2(b.w, b.w);
            #pragma unroll
            for (int q = 0; q < 4; q++) {
                unsigned long long a2 =
                    *(const unsigned long long*)&As[k][ty * 8 + 2 * q];
                fma2(acc2[q][0], a2, bb[0]);
                fma2(acc2[q][1], a2, bb[1]);
                fma2(acc2[q][2], a2, bb[2]);
                fma2(acc2[q][3], a2, bb[3]);
            }
        }
        __syncthreads();
    }
    float4 bias = ((const float4*)b2)[tx];
    #pragma unroll
    for (int q = 0; q < 4; q++) {
        float lo[4], hi[4];
        #pragma unroll
        for (int c = 0; c < 4; c++) unpack2(acc2[q][c], lo[c], hi[c]);
        int r0 = row0 + ty * 8 + 2 * q;
        if (r0 < N_NODES) {
            float4 v = make_float4(fmaxf(lo[0] + bias.x, 0.f),
                                   fmaxf(lo[1] + bias.y, 0.f),
                                   fmaxf(lo[2] + bias.z, 0.f),
                                   fmaxf(lo[3] + bias.w, 0.f));
            ((float4*)g_bufB)[r0 * 32 + tx] = v;
        }
        if (r0 + 1 < N_NODES) {
            float4 v = make_float4(fmaxf(hi[0] + bias.x, 0.f),
                                   fmaxf(hi[1] + bias.y, 0.f),
                                   fmaxf(hi[2] + bias.z, 0.f),
                                   fmaxf(hi[3] + bias.w, 0.f));
            ((float4*)g_bufB)[(r0 + 1) * 32 + tx] = v;
        }
    }
}

// pool sums from bufB (batch sorted -> local accumulation); also graph counts.
__global__ void k_pool(const void* batch) {
    int tid = threadIdx.x;
    int start = blockIdx.x * 128;
    int end = min(start + 128, N_NODES);
    if (start >= N_NODES) return;
    int is64 = g_is64;
    int curg = ld_idx(batch, start, is64);
    float acc = 0.f;
    int runlen = 0;
    for (int n = start; n < end; n++) {
        int g = ld_idx(batch, n, is64);
        if (g != curg) {
            atomicAdd(&g_pool[curg * 128 + tid], acc);
            if (tid == 0) atomicAdd(&g_gcnt[curg], runlen);
            acc = 0.f; runlen = 0;
            curg = g;
        }
        acc += g_bufB[n * 128 + tid];
        runlen++;
    }
    atomicAdd(&g_pool[curg * 128 + tid], acc);
    if (tid == 0) atomicAdd(&g_gcnt[curg], runlen);
}

__global__ void k_final(const float* __restrict__ Wfc,
                        const float* __restrict__ bfc,
                        float* __restrict__ out) {
    int tid = threadIdx.x;   // 1024 = 64*16
    int g = tid >> 4;
    int o = tid & 15;
    float c = (float)max(g_gcnt[g], 1);
    float s = 0.f;
    #pragma unroll 8
    for (int k = 0; k < 128; k++)
        s = fmaf(g_pool[g * 128 + k], Wfc[k * 16 + o], s);
    out[tid] = s / c + bfc[o];
}

// ---------------- launch ----------------------------------------------------
extern "C" void kernel_launch(void* const* d_in, const int* in_sizes, int n_in,
                              void* d_out, int out_size) {
    const float* x   = (const float*)d_in[0];
    const void*  ei  = d_in[1];
    const void*  bat = d_in[2];
    const float* W1  = (const float*)d_in[3];
    const float* b1  = (const float*)d_in[4];
    const float* W2  = (const float*)d_in[5];
    const float* b2  = (const float*)d_in[6];
    const float* Wfc = (const float*)d_in[7];
    const float* bfc = (const float*)d_in[8];
    float* out = (float*)d_out;

    k_init<<<(N_NODES + 255) / 256, 256>>>();                 // 1
    k_build<<<(N_EDGES + 255) / 256, 256>>>(ei);              // 2
    k_dinvxs<<<(N_NODES * 16 + 255) / 256, 256>>>(x);         // 3
    k_l1<<<(N_NODES * 32 + 255) / 256, 256>>>(W1, b1);        // 4  <- ncu slot
    k_aggh<<<(N_NODES + 7) / 8, 256>>>();                     // 5
    k_gemm2<<<(N_NODES + 63) / 64, 256>>>(W2, b2);            // 6
    k_pool<<<(N_NODES + 127) / 128, 128>>>(bat);              // 7
    k_final<<<1, 1024>>>(Wfc, bfc, out);                      // 8
}